// round 13
// baseline (speedup 1.0000x reference)
#include <cuda_runtime.h>
#include <cuda_fp16.h>
#include <cstdint>

// Problem constants
#define SS   96
#define BB   16
#define DD   512
#define HIDN 128
#define NR   (SS * BB)   // 1536 rows

// Intermediate activations
__device__ float g_ha[NR * HIDN];      // ha + b1
__device__ float g_hb[NR * HIDN];

// ---------------------------------------------------------------------------
// Helpers
// ---------------------------------------------------------------------------
__device__ __forceinline__ unsigned smem_u32(const void* p)
{
    unsigned a;
    asm("{ .reg .u64 t; cvta.to.shared.u64 t, %1; cvt.u32.u64 %0, t; }"
        : "=r"(a) : "l"(p));
    return a;
}

// SW128 swizzle (Swizzle<3,4,3>)
__device__ __forceinline__ unsigned sw128(unsigned byte_off)
{
    return byte_off ^ ((byte_off >> 3) & 0x70);
}

// Convert float4 -> 4 fp16 packed in uint2
__device__ __forceinline__ uint2 cvt_h4(float4 v)
{
    __half2 h01 = __float22half2_rn(make_float2(v.x, v.y));
    __half2 h23 = __float22half2_rn(make_float2(v.z, v.w));
    uint2 r;
    r.x = *reinterpret_cast<unsigned*>(&h01);
    r.y = *reinterpret_cast<unsigned*>(&h23);
    return r;
}

__device__ __forceinline__ void ldsm_x4(
    uint32_t& r0, uint32_t& r1, uint32_t& r2, uint32_t& r3, unsigned addr)
{
    asm volatile("ldmatrix.sync.aligned.m8n8.x4.shared.b16 {%0,%1,%2,%3}, [%4];"
                 : "=r"(r0), "=r"(r1), "=r"(r2), "=r"(r3) : "r"(addr));
}

__device__ __forceinline__ void mma_f16(
    float* d, uint32_t a0, uint32_t a1, uint32_t a2, uint32_t a3,
    uint32_t b0, uint32_t b1)
{
    asm volatile(
        "mma.sync.aligned.m16n8k16.row.col.f32.f16.f16.f32 "
        "{%0,%1,%2,%3}, {%4,%5,%6,%7}, {%8,%9}, {%0,%1,%2,%3};"
        : "+f"(d[0]), "+f"(d[1]), "+f"(d[2]), "+f"(d[3])
        : "r"(a0), "r"(a1), "r"(a2), "r"(a3), "r"(b0), "r"(b1));
}

// Packed f32x2 ops (stage2)
__device__ __forceinline__ unsigned long long add2(
    unsigned long long a, unsigned long long b)
{
    unsigned long long d;
    asm("add.rn.f32x2 %0, %1, %2;" : "=l"(d) : "l"(a), "l"(b));
    return d;
}
__device__ __forceinline__ unsigned long long ffma2(
    unsigned long long a, unsigned long long b, unsigned long long c)
{
    unsigned long long d;
    asm("fma.rn.f32x2 %0, %1, %2, %3;" : "=l"(d) : "l"(a), "l"(b), "l"(c));
    return d;
}
__device__ __forceinline__ unsigned long long relu2(unsigned long long x)
{
    unsigned long long r;
    asm("{\n\t.reg .f32 lo, hi;\n\t"
        "mov.b64 {lo, hi}, %1;\n\t"
        "max.f32 lo, lo, 0f00000000;\n\t"
        "max.f32 hi, hi, 0f00000000;\n\t"
        "mov.b64 %0, {lo, hi};\n\t}"
        : "=l"(r) : "l"(x));
    return r;
}
__device__ __forceinline__ float2 unpk2(unsigned long long v)
{
    float2 f;
    asm("mov.b64 {%0, %1}, %2;" : "=f"(f.x), "=f"(f.y) : "l"(v));
    return f;
}

// ---------------------------------------------------------------------------
// Stage 1: fp16 GEMM on mma.sync m16n8k16 (fp32 accumulate).
//   C[r][h] = sum_k X[r][k] * W[h][k]
// Block tile M=64, N=64. 8 warps = 2(m) x 4(n); warp tile 32x16.
// B (W tile, 64 rows x 512 k) is converted ONCE into smem (8 chunk tiles,
// 64KB); the main loop double-buffers only the A chunks (64x64 fp16 = 8KB).
// Grid (24, 2, 2) = 96 blocks, 256 threads.
// ---------------------------------------------------------------------------
#define S1_BREG   0          // 8 chunks x 8192 B = 64KB
#define S1_AREG   65536      // 2 buffers x 8192 B
#define S1_SMEM   81920

__global__ __launch_bounds__(256) void stage1_kernel(
    const float* __restrict__ X0, const float* __restrict__ X1,
    const float* __restrict__ W1, const float* __restrict__ b1)
{
    extern __shared__ char smem[];
    const unsigned sbase = smem_u32(smem);

    const int mt = blockIdx.x;   // 0..23
    const int nt = blockIdx.y;   // 0..1
    const int z  = blockIdx.z;   // 0..1
    const int m0 = mt * 64;
    const int n0 = nt * 64;

    const float* __restrict__ X = z ? X1 : X0;
    const float* __restrict__ W = W1 + (size_t)z * DD;   // row stride 2*DD
    float* __restrict__ C = z ? g_hb : g_ha;

    const int tid  = threadIdx.x;
    const int wid  = tid >> 5;
    const int lane = tid & 31;
    const int wm   = wid & 1;    // m offset wm*32
    const int wn   = wid >> 1;   // n offset wn*16

    // ---- One-time B fill: 64 rows x 512 k -> 8 chunk tiles, fp16 SW128 ----
    // 64 x 128 float4 = 8192 float4; 32 per thread; coalesced along k.
    #pragma unroll 8
    for (int i = 0; i < 32; i++) {
        const int flat = tid + i * 256;      // 0..8191
        const int row  = flat >> 7;          // 0..63
        const int q    = flat & 127;         // float4 index along k (0..127)
        const int ch   = q >> 4;             // chunk 0..7
        const int ql   = q & 15;             // local float4 index
        float4 v = *reinterpret_cast<const float4*>(
            &W[(size_t)(n0 + row) * (2 * DD) + q * 4]);
        const unsigned so = sw128((unsigned)(row * 128 + ql * 8));
        *reinterpret_cast<uint2*>(smem + S1_BREG + ch * 8192 + so) = cvt_h4(v);
    }

    // ---- A fill coords: 64 rows x 16 q = 1024 float4 -> 4/thread ----
    int arow[4], aq[4];
    #pragma unroll
    for (int i = 0; i < 4; i++) {
        const int flat = tid + i * 256;
        arow[i] = flat >> 4;  aq[i] = flat & 15;
    }

    // ldmatrix lane addressing
    const int a_r  = (lane & 15);
    const int a_ch = (lane >> 4);           // 0..1
    const int b_n  = (lane & 7) + ((lane >> 4) << 3);
    const int b_ch = (lane >> 3) & 1;

    float4 rA[4];

    // ---- prologue: A chunk 0 -> buf 0 ----
    #pragma unroll
    for (int i = 0; i < 4; i++)
        rA[i] = *reinterpret_cast<const float4*>(
            &X[(size_t)(m0 + arow[i]) * DD + aq[i] * 4]);
    #pragma unroll
    for (int i = 0; i < 4; i++) {
        const unsigned so = sw128((unsigned)(arow[i] * 128 + aq[i] * 8));
        *reinterpret_cast<uint2*>(smem + S1_AREG + so) = cvt_h4(rA[i]);
    }
    __syncthreads();

    float acc[2][2][4];
    #pragma unroll
    for (int mi = 0; mi < 2; mi++)
        #pragma unroll
        for (int ni = 0; ni < 2; ni++)
            #pragma unroll
            for (int r = 0; r < 4; r++) acc[mi][ni][r] = 0.0f;

    #pragma unroll 1
    for (int t = 0; t < 8; t++) {
        const unsigned aBuf = (unsigned)(S1_AREG + (t & 1) * 8192);

        // ---- LDG A chunk t+1 (hidden behind MMAs) ----
        if (t < 7) {
            const int k0 = (t + 1) * 64;
            #pragma unroll
            for (int i = 0; i < 4; i++)
                rA[i] = *reinterpret_cast<const float4*>(
                    &X[(size_t)(m0 + arow[i]) * DD + k0 + aq[i] * 4]);
        }

        // ---- MMAs: A buf t  x  B chunk t ----
        const unsigned aH = sbase + aBuf;
        const unsigned bH = sbase + (unsigned)(S1_BREG + t * 8192);

        #pragma unroll
        for (int ks = 0; ks < 4; ks++) {
            const unsigned kb = (unsigned)(ks * 32);

            uint32_t ah[2][4];
            #pragma unroll
            for (int mi = 0; mi < 2; mi++) {
                const unsigned off = sw128(
                    (unsigned)((wm * 32 + mi * 16 + a_r) * 128) + kb + a_ch * 16);
                ldsm_x4(ah[mi][0], ah[mi][1], ah[mi][2], ah[mi][3], aH + off);
            }
            uint32_t bh[4];
            {
                const unsigned off = sw128(
                    (unsigned)((wn * 16 + b_n) * 128) + kb + b_ch * 16);
                ldsm_x4(bh[0], bh[1], bh[2], bh[3], bH + off);
            }

            #pragma unroll
            for (int mi = 0; mi < 2; mi++)
                #pragma unroll
                for (int ni = 0; ni < 2; ni++)
                    mma_f16(acc[mi][ni], ah[mi][0], ah[mi][1], ah[mi][2], ah[mi][3],
                            bh[2 * ni], bh[2 * ni + 1]);
        }

        // ---- STS A chunk t+1 into other buffer, one sync ----
        if (t < 7) {
            const unsigned nbuf = (unsigned)(S1_AREG + ((t + 1) & 1) * 8192);
            #pragma unroll
            for (int i = 0; i < 4; i++) {
                const unsigned so = sw128((unsigned)(arow[i] * 128 + aq[i] * 8));
                *reinterpret_cast<uint2*>(smem + nbuf + so) = cvt_h4(rA[i]);
            }
            __syncthreads();
        }
    }

    // ---- Epilogue: write D fragments (+ b1 for z=0) ----
    #pragma unroll
    for (int mi = 0; mi < 2; mi++) {
        #pragma unroll
        for (int ni = 0; ni < 2; ni++) {
            const int row = m0 + wm * 32 + mi * 16 + (lane >> 2);
            const int col = n0 + wn * 16 + ni * 8 + (lane & 3) * 2;
            float2 bias = make_float2(0.f, 0.f);
            if (z == 0)
                bias = *reinterpret_cast<const float2*>(&b1[col]);
            float2 o0, o1;
            o0.x = acc[mi][ni][0] + bias.x;
            o0.y = acc[mi][ni][1] + bias.y;
            o1.x = acc[mi][ni][2] + bias.x;
            o1.y = acc[mi][ni][3] + bias.y;
            *reinterpret_cast<float2*>(&C[(size_t)row * HIDN + col]) = o0;
            *reinterpret_cast<float2*>(&C[(size_t)(row + 8) * HIDN + col]) = o1;
        }
    }
}

// ---------------------------------------------------------------------------
// Stage 2: out[i,j,b,c] = sum_h relu(ha'[i,b,h]+hb[j,b,h])*W2[c,h]+b2[c]
// Grid (3,3,16): 32x32 (i,j) tile at fixed b, 256 threads, 2x2 per thread.
// Packed along h (add2/relu2/ffma2). hq loop only PARTIALLY unrolled (8) so
// the body stays L0-I$-resident (~6KB) instead of streaming ~23KB per pass.
// ---------------------------------------------------------------------------
#define TI 32
#define TJ 32
#define PADH 132  // 128+4 -> reduced bank conflicts, 16B aligned

__global__ __launch_bounds__(256) void stage2_kernel(
    const float* __restrict__ W2, const float* __restrict__ b2,
    float* __restrict__ out)
{
    __shared__ float sA[TI][PADH];
    __shared__ float sB[TJ][PADH];
    __shared__ float sW2[2 * HIDN];

    const int i0  = blockIdx.x * TI;
    const int j0  = blockIdx.y * TJ;
    const int b   = blockIdx.z;
    const int tid = threadIdx.x;

    #pragma unroll
    for (int i = 0; i < 4; i++) {
        const int q   = tid + i * 256;  // 0..1023
        const int row = q >> 5;         // 0..31
        const int hq  = q & 31;         // float4 index along h

        float4 va = *reinterpret_cast<const float4*>(
            &g_ha[((size_t)(i0 + row) * BB + b) * HIDN + hq * 4]);
        *reinterpret_cast<float4*>(&sA[row][hq * 4]) = va;

        float4 vb = *reinterpret_cast<const float4*>(
            &g_hb[((size_t)(j0 + row) * BB + b) * HIDN + hq * 4]);
        *reinterpret_cast<float4*>(&sB[row][hq * 4]) = vb;
    }
    if (tid < 64) {
        float4 w = *reinterpret_cast<const float4*>(&W2[tid * 4]);
        *reinterpret_cast<float4*>(&sW2[tid * 4]) = w;
    }
    __syncthreads();

    const int rg = tid >> 4;   // 0..15 -> i rows rg, rg+16
    const int cg = tid & 15;   // 0..15 -> j cols cg, cg+16

    // acc[ii][jj][c]: packed (even-h, odd-h) partial sums for channel c
    unsigned long long acc[2][2][2];
    #pragma unroll
    for (int ii = 0; ii < 2; ii++)
        #pragma unroll
        for (int jj = 0; jj < 2; jj++) {
            acc[ii][jj][0] = 0ull;
            acc[ii][jj][1] = 0ull;
        }

    #pragma unroll 8
    for (int hq = 0; hq < HIDN / 4; hq++) {
        ulonglong2 a0 = *reinterpret_cast<const ulonglong2*>(&sA[rg][hq * 4]);
        ulonglong2 a1 = *reinterpret_cast<const ulonglong2*>(&sA[rg + 16][hq * 4]);
        ulonglong2 q0 = *reinterpret_cast<const ulonglong2*>(&sB[cg][hq * 4]);
        ulonglong2 q1 = *reinterpret_cast<const ulonglong2*>(&sB[cg + 16][hq * 4]);
        ulonglong2 w0 = *reinterpret_cast<const ulonglong2*>(&sW2[hq * 4]);
        ulonglong2 w1 = *reinterpret_cast<const ulonglong2*>(&sW2[HIDN + hq * 4]);

        const unsigned long long av[2][2] = {{a0.x, a0.y}, {a1.x, a1.y}};
        const unsigned long long qv[2][2] = {{q0.x, q0.y}, {q1.x, q1.y}};
        const unsigned long long wv[2][2] = {{w0.x, w0.y}, {w1.x, w1.y}};

        #pragma unroll
        for (int hp = 0; hp < 2; hp++) {
            #pragma unroll
            for (int ii = 0; ii < 2; ii++)
                #pragma unroll
                for (int jj = 0; jj < 2; jj++) {
                    unsigned long long v = relu2(add2(av[ii][hp], qv[jj][hp]));
                    acc[ii][jj][0] = ffma2(v, wv[0][hp], acc[ii][jj][0]);
                    acc[ii][jj][1] = ffma2(v, wv[1][hp], acc[ii][jj][1]);
                }
        }
    }

    const float bb0 = b2[0];
    const float bb1 = b2[1];
    #pragma unroll
    for (int ii = 0; ii < 2; ii++)
        #pragma unroll
        for (int jj = 0; jj < 2; jj++) {
            const int i = i0 + rg + ii * 16;
            const int j = j0 + cg + jj * 16;
            const size_t idx = (((size_t)i * SS + j) * BB + b) * 2;
            float2 p0 = unpk2(acc[ii][jj][0]);
            float2 p1 = unpk2(acc[ii][jj][1]);
            float2 o;
            o.x = p0.x + p0.y + bb0;
            o.y = p1.x + p1.y + bb1;
            *reinterpret_cast<float2*>(&out[idx]) = o;
        }
}

// ---------------------------------------------------------------------------
// Inputs: embeds, umask, qmask, embeds_cmp, W1, b1, W2, b2
// ---------------------------------------------------------------------------
extern "C" void kernel_launch(void* const* d_in, const int* in_sizes, int n_in,
                              void* d_out, int out_size)
{
    const float* embeds     = (const float*)d_in[0];
    const float* embeds_cmp = (const float*)d_in[3];
    const float* W1         = (const float*)d_in[4];
    const float* b1         = (const float*)d_in[5];
    const float* W2         = (const float*)d_in[6];
    const float* b2         = (const float*)d_in[7];
    float* out = (float*)d_out;

    cudaFuncSetAttribute(stage1_kernel,
                         cudaFuncAttributeMaxDynamicSharedMemorySize, S1_SMEM);

    stage1_kernel<<<dim3(24, 2, 2), 256, S1_SMEM>>>(embeds, embeds_cmp, W1, b1);
    stage2_kernel<<<dim3(3, 3, 16), 256>>>(W2, b2, out);
}

// round 15
// speedup vs baseline: 1.0542x; 1.0542x over previous
#include <cuda_runtime.h>
#include <cuda_fp16.h>
#include <cstdint>

// Problem constants
#define SS   96
#define BB   16
#define DD   512
#define HIDN 128
#define NR   (SS * BB)   // 1536 rows
#define NCH  8           // k chunks of 64

// Intermediate activations
__device__ float g_ha[NR * HIDN];
__device__ float g_hb[NR * HIDN];

// Pre-converted, pre-swizzled fp16 operands.
// Layout: chunk-major 128B rows, each row ALREADY in SW128 smem image:
//   X16[z]: byte offset ((c*NR + r)*128) + (ql*8 ^ ((r&7)<<4))   for f4-group ql
//   W16[z]: byte offset ((c*HIDN + h)*128) + (ql*8 ^ ((h&7)<<4))
__device__ __align__(256) __half g_X16[2][NCH * NR * 64];
__device__ __align__(256) __half g_W16[2][NCH * HIDN * 64];

// ---------------------------------------------------------------------------
// Helpers
// ---------------------------------------------------------------------------
__device__ __forceinline__ unsigned smem_u32(const void* p)
{
    unsigned a;
    asm("{ .reg .u64 t; cvta.to.shared.u64 t, %1; cvt.u32.u64 %0, t; }"
        : "=r"(a) : "l"(p));
    return a;
}

__device__ __forceinline__ unsigned sw128(unsigned byte_off)
{
    return byte_off ^ ((byte_off >> 3) & 0x70);
}

__device__ __forceinline__ uint2 cvt_h4(float4 v)
{
    __half2 h01 = __float22half2_rn(make_float2(v.x, v.y));
    __half2 h23 = __float22half2_rn(make_float2(v.z, v.w));
    uint2 r;
    r.x = *reinterpret_cast<unsigned*>(&h01);
    r.y = *reinterpret_cast<unsigned*>(&h23);
    return r;
}

__device__ __forceinline__ void ldsm_x4(
    uint32_t& r0, uint32_t& r1, uint32_t& r2, uint32_t& r3, unsigned addr)
{
    asm volatile("ldmatrix.sync.aligned.m8n8.x4.shared.b16 {%0,%1,%2,%3}, [%4];"
                 : "=r"(r0), "=r"(r1), "=r"(r2), "=r"(r3) : "r"(addr));
}

__device__ __forceinline__ void mma_f16(
    float* d, uint32_t a0, uint32_t a1, uint32_t a2, uint32_t a3,
    uint32_t b0, uint32_t b1)
{
    asm volatile(
        "mma.sync.aligned.m16n8k16.row.col.f32.f16.f16.f32 "
        "{%0,%1,%2,%3}, {%4,%5,%6,%7}, {%8,%9}, {%0,%1,%2,%3};"
        : "+f"(d[0]), "+f"(d[1]), "+f"(d[2]), "+f"(d[3])
        : "r"(a0), "r"(a1), "r"(a2), "r"(a3), "r"(b0), "r"(b1));
}

__device__ __forceinline__ void cp16(unsigned dst, const void* src)
{
    asm volatile("cp.async.cg.shared.global [%0], [%1], 16;" :: "r"(dst), "l"(src));
}
__device__ __forceinline__ void cp_commit() { asm volatile("cp.async.commit_group;"); }
__device__ __forceinline__ void cp_wait1()  { asm volatile("cp.async.wait_group 1;"); }
__device__ __forceinline__ void cp_wait0()  { asm volatile("cp.async.wait_group 0;"); }

// Packed f32x2 ops (stage2)
__device__ __forceinline__ unsigned long long add2(
    unsigned long long a, unsigned long long b)
{
    unsigned long long d;
    asm("add.rn.f32x2 %0, %1, %2;" : "=l"(d) : "l"(a), "l"(b));
    return d;
}
__device__ __forceinline__ unsigned long long ffma2(
    unsigned long long a, unsigned long long b, unsigned long long c)
{
    unsigned long long d;
    asm("fma.rn.f32x2 %0, %1, %2, %3;" : "=l"(d) : "l"(a), "l"(b), "l"(c));
    return d;
}
__device__ __forceinline__ unsigned long long relu2(unsigned long long x)
{
    unsigned long long r;
    asm("{\n\t.reg .f32 lo, hi;\n\t"
        "mov.b64 {lo, hi}, %1;\n\t"
        "max.f32 lo, lo, 0f00000000;\n\t"
        "max.f32 hi, hi, 0f00000000;\n\t"
        "mov.b64 %0, {lo, hi};\n\t}"
        : "=l"(r) : "l"(x));
    return r;
}
__device__ __forceinline__ float2 unpk2(unsigned long long v)
{
    float2 f;
    asm("mov.b64 {%0, %1}, %2;" : "=f"(f.x), "=f"(f.y) : "l"(v));
    return f;
}

// ---------------------------------------------------------------------------
// Prep kernel: convert X0/X1/W1 to fp16, pre-swizzled chunk-row layout.
// X part: 2 * 1536 * 128 f4 = 393216 threads; W part: 2 * 128 * 128 = 32768.
// Grid 1664 x 256.
// ---------------------------------------------------------------------------
#define PREP_X_TOTAL (2 * NR * 128)
#define PREP_W_TOTAL (2 * HIDN * 128)

__global__ __launch_bounds__(256) void prep_kernel(
    const float* __restrict__ X0, const float* __restrict__ X1,
    const float* __restrict__ W1)
{
    const int idx = blockIdx.x * 256 + threadIdx.x;
    if (idx < PREP_X_TOTAL) {
        const int z = idx >= (NR * 128);
        const int i = idx - z * (NR * 128);
        const int r = i >> 7;        // 0..1535
        const int q = i & 127;       // f4 index along k
        const float* __restrict__ X = z ? X1 : X0;
        float4 v = *reinterpret_cast<const float4*>(&X[(size_t)r * DD + q * 4]);
        const int c  = q >> 4;
        const int ql = q & 15;
        const unsigned dst = (unsigned)((c * NR + r) * 128)
                           + ((unsigned)(ql * 8) ^ ((unsigned)(r & 7) << 4));
        *reinterpret_cast<uint2*>(
            reinterpret_cast<char*>(g_X16[z]) + dst) = cvt_h4(v);
    } else if (idx < PREP_X_TOTAL + PREP_W_TOTAL) {
        const int j = idx - PREP_X_TOTAL;
        const int z = j >= (HIDN * 128);
        const int i = j - z * (HIDN * 128);
        const int h = i >> 7;        // 0..127
        const int q = i & 127;
        float4 v = *reinterpret_cast<const float4*>(
            &W1[(size_t)h * (2 * DD) + z * DD + q * 4]);
        const int c  = q >> 4;
        const int ql = q & 15;
        const unsigned dst = (unsigned)((c * HIDN + h) * 128)
                           + ((unsigned)(ql * 8) ^ ((unsigned)(h & 7) << 4));
        *reinterpret_cast<uint2*>(
            reinterpret_cast<char*>(g_W16[z]) + dst) = cvt_h4(v);
    }
}

// ---------------------------------------------------------------------------
// Stage 1: fp16 GEMM, pure cp.async fills (operands preconverted+preswizzled).
// Block tile M=32, N=64; 8 warps = 2(m) x 4(n); warp tile 16x16.
// 3-buffer cp.async pipeline over 8 k-chunks; one __syncthreads per chunk.
// Grid (48, 2, 2) = 192 blocks, 256 threads.
// ---------------------------------------------------------------------------
#define SA_BYTES 4096    // 32 rows x 128B
#define SB_BYTES 8192    // 64 rows x 128B
#define SA_OFF(i) ((i) * SA_BYTES)
#define SB_OFF(i) (3 * SA_BYTES + (i) * SB_BYTES)
#define S1_SMEM  (3 * SA_BYTES + 3 * SB_BYTES)   // 36864

__global__ __launch_bounds__(256) void stage1_kernel(const float* __restrict__ b1)
{
    extern __shared__ char smem[];
    const unsigned sbase = smem_u32(smem);

    const int mt = blockIdx.x;   // 0..47
    const int nt = blockIdx.y;   // 0..1
    const int z  = blockIdx.z;   // 0..1
    const int m0 = mt * 32;
    const int n0 = nt * 64;

    const char* __restrict__ Xg = reinterpret_cast<const char*>(g_X16[z]);
    const char* __restrict__ Wg = reinterpret_cast<const char*>(g_W16[z]);
    float* __restrict__ C = z ? g_hb : g_ha;

    const int tid  = threadIdx.x;
    const int wid  = tid >> 5;
    const int lane = tid & 31;
    const int wm   = wid & 1;    // m offset wm*16
    const int wn   = wid >> 1;   // n offset wn*16

    // Fill mapping (verbatim 16B copies of pre-swizzled rows):
    // A: 32 rows x 8 segs = 256 -> 1/thread. B: 64 rows x 8 segs = 512 -> 2/thread.
    const int a_row = tid >> 3;          // 0..31
    const int a_seg = tid & 7;           // 16B segment
    const unsigned aDst = a_row * 128u + a_seg * 16u;
    const int b_row0 = tid >> 3;         // 0..31
    const int b_row1 = (tid + 256) >> 3; // 32..63
    const int b_seg  = tid & 7;
    const unsigned bDst0 = b_row0 * 128u + b_seg * 16u;
    const unsigned bDst1 = b_row1 * 128u + b_seg * 16u;

    auto fill = [&](int c, int buf) {
        cp16(sbase + SA_OFF(buf) + aDst,
             Xg + (size_t)(c * NR + m0 + a_row) * 128 + a_seg * 16);
        cp16(sbase + SB_OFF(buf) + bDst0,
             Wg + (size_t)(c * HIDN + n0 + b_row0) * 128 + b_seg * 16);
        cp16(sbase + SB_OFF(buf) + bDst1,
             Wg + (size_t)(c * HIDN + n0 + b_row1) * 128 + b_seg * 16);
        cp_commit();
    };

    // prologue: chunks 0 and 1
    fill(0, 0);
    fill(1, 1);

    // ldmatrix lane addressing
    const int a_r  = (lane & 15);
    const int a_ch = (lane >> 4);           // 0..1
    const int b_n  = (lane & 7) + ((lane >> 4) << 3);
    const int b_ch = (lane >> 3) & 1;

    float acc[2][4];
    #pragma unroll
    for (int ni = 0; ni < 2; ni++)
        #pragma unroll
        for (int r = 0; r < 4; r++) acc[ni][r] = 0.0f;

    #pragma unroll 1
    for (int t = 0; t < NCH; t++) {
        if (t < NCH - 1) cp_wait1(); else cp_wait0();
        __syncthreads();

        // issue chunk t+2 into buffer (t+2)%3 (last read at iter t-1; safe)
        if (t + 2 < NCH) fill(t + 2, (t + 2) % 3);

        const unsigned aH = sbase + SA_OFF(t % 3);
        const unsigned bH = sbase + SB_OFF(t % 3);

        #pragma unroll
        for (int ks = 0; ks < 4; ks++) {
            const unsigned kb = (unsigned)(ks * 32);
            uint32_t ah[4];
            {
                const unsigned off = sw128(
                    (unsigned)((wm * 16 + a_r) * 128) + kb + a_ch * 16);
                ldsm_x4(ah[0], ah[1], ah[2], ah[3], aH + off);
            }
            uint32_t bh[4];
            {
                const unsigned off = sw128(
                    (unsigned)((wn * 16 + b_n) * 128) + kb + b_ch * 16);
                ldsm_x4(bh[0], bh[1], bh[2], bh[3], bH + off);
            }
            #pragma unroll
            for (int ni = 0; ni < 2; ni++)
                mma_f16(acc[ni], ah[0], ah[1], ah[2], ah[3],
                        bh[2 * ni], bh[2 * ni + 1]);
        }
    }

    // ---- Epilogue: write D fragments (+ b1 for z=0) ----
    #pragma unroll
    for (int ni = 0; ni < 2; ni++) {
        const int row = m0 + wm * 16 + (lane >> 2);
        const int col = n0 + wn * 16 + ni * 8 + (lane & 3) * 2;
        float2 bias = make_float2(0.f, 0.f);
        if (z == 0)
            bias = *reinterpret_cast<const float2*>(&b1[col]);
        float2 o0, o1;
        o0.x = acc[ni][0] + bias.x;
        o0.y = acc[ni][1] + bias.y;
        o1.x = acc[ni][2] + bias.x;
        o1.y = acc[ni][3] + bias.y;
        *reinterpret_cast<float2*>(&C[(size_t)row * HIDN + col]) = o0;
        *reinterpret_cast<float2*>(&C[(size_t)(row + 8) * HIDN + col]) = o1;
    }
}

// ---------------------------------------------------------------------------
// Stage 2 (R8 measured-best variant, verbatim):
// out[i,j,b,c] = sum_h relu(ha'[i,b,h]+hb[j,b,h])*W2[c,h]+b2[c]
// Grid (3,3,16): 32x32 (i,j) tile at fixed b, 256 threads, 2x2 per thread.
// ---------------------------------------------------------------------------
#define TI 32
#define TJ 32
#define PADH 132

__global__ __launch_bounds__(256) void stage2_kernel(
    const float* __restrict__ W2, const float* __restrict__ b2,
    float* __restrict__ out)
{
    __shared__ float sA[TI][PADH];
    __shared__ float sB[TJ][PADH];
    __shared__ float sW2[2 * HIDN];

    const int i0  = blockIdx.x * TI;
    const int j0  = blockIdx.y * TJ;
    const int b   = blockIdx.z;
    const int tid = threadIdx.x;

    #pragma unroll
    for (int i = 0; i < 4; i++) {
        const int q   = tid + i * 256;  // 0..1023
        const int row = q >> 5;         // 0..31
        const int hq  = q & 31;
        float4 va = *reinterpret_cast<const float4*>(
            &g_ha[((size_t)(i0 + row) * BB + b) * HIDN + hq * 4]);
        *reinterpret_cast<float4*>(&sA[row][hq * 4]) = va;
        float4 vb = *reinterpret_cast<const float4*>(
            &g_hb[((size_t)(j0 + row) * BB + b) * HIDN + hq * 4]);
        *reinterpret_cast<float4*>(&sB[row][hq * 4]) = vb;
    }
    if (tid < 64) {
        float4 w = *reinterpret_cast<const float4*>(&W2[tid * 4]);
        *reinterpret_cast<float4*>(&sW2[tid * 4]) = w;
    }
    __syncthreads();

    const int rg = tid >> 4;
    const int cg = tid & 15;

    unsigned long long acc[2][2][2];
    #pragma unroll
    for (int ii = 0; ii < 2; ii++)
        #pragma unroll
        for (int jj = 0; jj < 2; jj++) {
            acc[ii][jj][0] = 0ull;
            acc[ii][jj][1] = 0ull;
        }

    #pragma unroll
    for (int hq = 0; hq < HIDN / 4; hq++) {
        ulonglong2 a0 = *reinterpret_cast<const ulonglong2*>(&sA[rg][hq * 4]);
        ulonglong2 a1 = *reinterpret_cast<const ulonglong2*>(&sA[rg + 16][hq * 4]);
        ulonglong2 q0 = *reinterpret_cast<const ulonglong2*>(&sB[cg][hq * 4]);
        ulonglong2 q1 = *reinterpret_cast<const ulonglong2*>(&sB[cg + 16][hq * 4]);
        ulonglong2 w0 = *reinterpret_cast<const ulonglong2*>(&sW2[hq * 4]);
        ulonglong2 w1 = *reinterpret_cast<const ulonglong2*>(&sW2[HIDN + hq * 4]);

        const unsigned long long av[2][2] = {{a0.x, a0.y}, {a1.x, a1.y}};
        const unsigned long long qv[2][2] = {{q0.x, q0.y}, {q1.x, q1.y}};
        const unsigned long long wv[2][2] = {{w0.x, w0.y}, {w1.x, w1.y}};

        #pragma unroll
        for (int hp = 0; hp < 2; hp++) {
            #pragma unroll
            for (int ii = 0; ii < 2; ii++)
                #pragma unroll
                for (int jj = 0; jj < 2; jj++) {
                    unsigned long long v = relu2(add2(av[ii][hp], qv[jj][hp]));
                    acc[ii][jj][0] = ffma2(v, wv[0][hp], acc[ii][jj][0]);
                    acc[ii][jj][1] = ffma2(v, wv[1][hp], acc[ii][jj][1]);
                }
        }
    }

    const float bb0 = b2[0];
    const float bb1 = b2[1];
    #pragma unroll
    for (int ii = 0; ii < 2; ii++)
        #pragma unroll
        for (int jj = 0; jj < 2; jj++) {
            const int i = i0 + rg + ii * 16;
            const int j = j0 + cg + jj * 16;
            const size_t idx = (((size_t)i * SS + j) * BB + b) * 2;
            float2 p0 = unpk2(acc[ii][jj][0]);
            float2 p1 = unpk2(acc[ii][jj][1]);
            float2 o;
            o.x = p0.x + p0.y + bb0;
            o.y = p1.x + p1.y + bb1;
            *reinterpret_cast<float2*>(&out[idx]) = o;
        }
}

// ---------------------------------------------------------------------------
// Inputs: embeds, umask, qmask, embeds_cmp, W1, b1, W2, b2
// ---------------------------------------------------------------------------
extern "C" void kernel_launch(void* const* d_in, const int* in_sizes, int n_in,
                              void* d_out, int out_size)
{
    const float* embeds     = (const float*)d_in[0];
    const float* embeds_cmp = (const float*)d_in[3];
    const float* W1         = (const float*)d_in[4];
    const float* b1         = (const float*)d_in[5];
    const float* W2         = (const float*)d_in[6];
    const float* b2         = (const float*)d_in[7];
    float* out = (float*)d_out;

    cudaFuncSetAttribute(stage1_kernel,
                         cudaFuncAttributeMaxDynamicSharedMemorySize, S1_SMEM);

    const int prep_blocks = (PREP_X_TOTAL + PREP_W_TOTAL + 255) / 256;
    prep_kernel<<<prep_blocks, 256>>>(embeds, embeds_cmp, W1);
    stage1_kernel<<<dim3(48, 2, 2), 256, S1_SMEM>>>(b1);
    stage2_kernel<<<dim3(3, 3, 16), 256>>>(W2, b2, out);
}